// round 1
// baseline (speedup 1.0000x reference)
#include <cuda_runtime.h>

// Problem shape (fixed by the dataset)
#define BB  64
#define TT  4096
#define HH  1024
#define NHH 4

// Scratch for h = x @ W^T + b : [B, T, NH] = 1,048,576 floats = 4 MB
__device__ float g_h[BB * TT * NHH];

// ---------------------------------------------------------------------------
// Kernel 1: tall-skinny GEMV. One warp computes 4 consecutive (b,t) rows,
// each row = 4 dot products of length 1024 against W (staged in smem).
// float4 loads throughout; W reused across the 4 rows to keep L1 traffic low.
// ---------------------------------------------------------------------------
__global__ __launch_bounds__(256) void k_gemv(const float* __restrict__ x,
                                              const float* __restrict__ W,
                                              const float* __restrict__ bias) {
    __shared__ float4 sW[NHH * (HH / 4)];  // 4 * 256 float4 = 16 KB
    for (int i = threadIdx.x; i < NHH * (HH / 4); i += 256)
        sW[i] = reinterpret_cast<const float4*>(W)[i];
    __syncthreads();

    const int ROWS = 4;
    int warp_global = (blockIdx.x * 256 + threadIdx.x) >> 5;
    int lane = threadIdx.x & 31;
    long row0 = (long)warp_global * ROWS;
    if (row0 >= (long)BB * TT) return;

    float acc[ROWS][NHH];
#pragma unroll
    for (int r = 0; r < ROWS; r++)
#pragma unroll
        for (int n = 0; n < NHH; n++) acc[r][n] = 0.0f;

    const float4* xp = reinterpret_cast<const float4*>(x) + row0 * (HH / 4);

#pragma unroll
    for (int k = 0; k < (HH / 4) / 32; k++) {  // 8 iterations
        int idx = lane + k * 32;
        float4 w0 = sW[0 * (HH / 4) + idx];
        float4 w1 = sW[1 * (HH / 4) + idx];
        float4 w2 = sW[2 * (HH / 4) + idx];
        float4 w3 = sW[3 * (HH / 4) + idx];
#pragma unroll
        for (int r = 0; r < ROWS; r++) {
            float4 xv = xp[(long)r * (HH / 4) + idx];
            acc[r][0] += xv.x * w0.x + xv.y * w0.y + xv.z * w0.z + xv.w * w0.w;
            acc[r][1] += xv.x * w1.x + xv.y * w1.y + xv.z * w1.z + xv.w * w1.w;
            acc[r][2] += xv.x * w2.x + xv.y * w2.y + xv.z * w2.z + xv.w * w2.w;
            acc[r][3] += xv.x * w3.x + xv.y * w3.y + xv.z * w3.z + xv.w * w3.w;
        }
    }

    // Warp butterfly reductions
#pragma unroll
    for (int r = 0; r < ROWS; r++)
#pragma unroll
        for (int n = 0; n < NHH; n++)
#pragma unroll
            for (int off = 16; off > 0; off >>= 1)
                acc[r][n] += __shfl_xor_sync(0xffffffffu, acc[r][n], off);

    if (lane == 0) {
        float b0 = bias[0], b1 = bias[1], b2 = bias[2], b3 = bias[3];
#pragma unroll
        for (int r = 0; r < ROWS; r++) {
            float4 o = make_float4(acc[r][0] + b0, acc[r][1] + b1,
                                   acc[r][2] + b2, acc[r][3] + b3);
            reinterpret_cast<float4*>(g_h)[row0 + r] = o;  // 16B coalesced row store
        }
    }
}

// ---------------------------------------------------------------------------
// Kernel 2: chunked parallel EMA scan + running max + head projection.
// 64 blocks (one per batch), 4 warps (one per head). Each lane owns a
// 128-step chunk of T=4096. Two-pass: (1) per-chunk affine offset, Kogge-Stone
// affine-map scan across lanes for the incoming state, (2) serial replay with
// correct incoming state, tracking the max (init 0 to match reference).
// ---------------------------------------------------------------------------
__global__ __launch_bounds__(128) void k_scan(const float* __restrict__ decay,
                                              const float* __restrict__ head_w,
                                              float* __restrict__ out) {
    int b = blockIdx.x;
    int n = threadIdx.x >> 5;   // head
    int lane = threadIdx.x & 31;

    float d = 1.0f / (1.0f + expf(-decay[n]));
    float od = 1.0f - d;

    const int CH = TT / 32;  // 128 timesteps per lane
    const float* __restrict__ hp = g_h + (size_t)b * TT * NHH + n;
    int t0 = lane * CH;

    // Pass 1: chunk offset (ema starting from 0)
    float ema = 0.0f;
#pragma unroll 8
    for (int i = 0; i < CH; i++)
        ema = d * ema + od * hp[(t0 + i) * NHH];

    // A = d^128 by repeated squaring
    float A = d;
#pragma unroll
    for (int s = 0; s < 7; s++) A = A * A;

    // Inclusive Kogge-Stone scan of affine maps (a, b): e -> a*e + b
    float a = A, bq = ema;
#pragma unroll
    for (int off = 1; off < 32; off <<= 1) {
        float ap = __shfl_up_sync(0xffffffffu, a, off);
        float bp = __shfl_up_sync(0xffffffffu, bq, off);
        if (lane >= off) { bq = a * bp + bq; a = a * ap; }
    }
    float e_in = __shfl_up_sync(0xffffffffu, bq, 1);
    if (lane == 0) e_in = 0.0f;

    // Pass 2: replay with correct incoming state, track max (init 0: the
    // reference's ema_max starts at zeros and maxes after each update)
    ema = e_in;
    float emax = 0.0f;
#pragma unroll 8
    for (int i = 0; i < CH; i++) {
        ema = d * ema + od * hp[(t0 + i) * NHH];
        emax = fmaxf(emax, ema);
    }
#pragma unroll
    for (int off = 16; off > 0; off >>= 1)
        emax = fmaxf(emax, __shfl_xor_sync(0xffffffffu, emax, off));

    __shared__ float part[NHH];
    if (lane == 0) part[n] = emax * head_w[n];  // head_w shape (1, NH)
    __syncthreads();
    if (threadIdx.x == 0)
        out[b] = part[0] + part[1] + part[2] + part[3];
}

// ---------------------------------------------------------------------------
extern "C" void kernel_launch(void* const* d_in, const int* in_sizes, int n_in,
                              void* d_out, int out_size) {
    const float* x      = (const float*)d_in[0];  // [B, T, H]
    const float* W      = (const float*)d_in[1];  // [NH, H]
    const float* bias   = (const float*)d_in[2];  // [NH]
    const float* decay  = (const float*)d_in[3];  // [NH]
    const float* head_w = (const float*)d_in[4];  // [1, NH]
    float* out = (float*)d_out;                   // [B]

    // B*T = 262144 rows, 4 rows/warp -> 65536 warps -> 8192 blocks of 8 warps
    int warps = (BB * TT) / 4;
    int blocks = (warps * 32) / 256;
    k_gemv<<<blocks, 256>>>(x, W, bias);
    k_scan<<<BB, 128>>>(decay, head_w, out);
}

// round 3
// speedup vs baseline: 1.1207x; 1.1207x over previous
#include <cuda_runtime.h>

#define BB  64
#define TT  4096
#define HH  1024
#define NHH 4

// Scratch: h = x @ W^T + b : [B, T, NH] = 4 MB (stays L2-resident)
__device__ float g_h[BB * TT * NHH];
// Per-(b,head) running-max partials
__device__ float g_part[BB * NHH];

// ---------------------------------------------------------------------------
// Kernel 1: tall-skinny GEMV. One warp computes 4 consecutive (b,t) rows,
// each row = 4 dot products of length 1024 against W (staged in smem).
// ---------------------------------------------------------------------------
__global__ __launch_bounds__(256) void k_gemv(const float* __restrict__ x,
                                              const float* __restrict__ W,
                                              const float* __restrict__ bias) {
    __shared__ float4 sW[NHH * (HH / 4)];  // 16 KB
    for (int i = threadIdx.x; i < NHH * (HH / 4); i += 256)
        sW[i] = reinterpret_cast<const float4*>(W)[i];
    __syncthreads();

    const int ROWS = 4;
    int warp_global = (blockIdx.x * 256 + threadIdx.x) >> 5;
    int lane = threadIdx.x & 31;
    long row0 = (long)warp_global * ROWS;
    if (row0 >= (long)BB * TT) return;

    float acc[ROWS][NHH];
#pragma unroll
    for (int r = 0; r < ROWS; r++)
#pragma unroll
        for (int n = 0; n < NHH; n++) acc[r][n] = 0.0f;

    const float4* xp = reinterpret_cast<const float4*>(x) + row0 * (HH / 4);

#pragma unroll
    for (int k = 0; k < (HH / 4) / 32; k++) {  // 8 iterations
        int idx = lane + k * 32;
        float4 w0 = sW[0 * (HH / 4) + idx];
        float4 w1 = sW[1 * (HH / 4) + idx];
        float4 w2 = sW[2 * (HH / 4) + idx];
        float4 w3 = sW[3 * (HH / 4) + idx];
#pragma unroll
        for (int r = 0; r < ROWS; r++) {
            float4 xv = xp[(long)r * (HH / 4) + idx];
            acc[r][0] += xv.x * w0.x + xv.y * w0.y + xv.z * w0.z + xv.w * w0.w;
            acc[r][1] += xv.x * w1.x + xv.y * w1.y + xv.z * w1.z + xv.w * w1.w;
            acc[r][2] += xv.x * w2.x + xv.y * w2.y + xv.z * w2.z + xv.w * w2.w;
            acc[r][3] += xv.x * w3.x + xv.y * w3.y + xv.z * w3.z + xv.w * w3.w;
        }
    }

#pragma unroll
    for (int r = 0; r < ROWS; r++)
#pragma unroll
        for (int n = 0; n < NHH; n++)
#pragma unroll
            for (int off = 16; off > 0; off >>= 1)
                acc[r][n] += __shfl_xor_sync(0xffffffffu, acc[r][n], off);

    if (lane == 0) {
        float b0 = bias[0], b1 = bias[1], b2 = bias[2], b3 = bias[3];
#pragma unroll
        for (int r = 0; r < ROWS; r++) {
            float4 o = make_float4(acc[r][0] + b0, acc[r][1] + b1,
                                   acc[r][2] + b2, acc[r][3] + b3);
            reinterpret_cast<float4*>(g_h)[row0 + r] = o;
        }
    }
}

// ---------------------------------------------------------------------------
// Kernel 2: chunked parallel EMA scan + running max.
// Grid (B, NH) = 256 blocks, 256 threads each. Each thread owns a 16-step
// chunk. Two-level affine-map scan: warp Kogge-Stone + smem combine across
// the 8 warp aggregates; then a 16-step replay tracking the running max.
// ---------------------------------------------------------------------------
__global__ __launch_bounds__(256) void k_scan(const float* __restrict__ decay) {
    const int CH = TT / 256;  // 16
    int b = blockIdx.x, n = blockIdx.y;
    int tid = threadIdx.x;
    int wid = tid >> 5, lane = tid & 31;

    float d = 1.0f / (1.0f + expf(-decay[n]));
    float od = 1.0f - d;

    const float* __restrict__ hp = g_h + (size_t)b * TT * NHH + n;
    int t0 = tid * CH;

    // Pass 1: local chunk EMA starting from 0 (loads independent -> MLP=16)
    float ema = 0.0f;
#pragma unroll
    for (int i = 0; i < CH; i++)
        ema = d * ema + od * __ldg(&hp[(t0 + i) * NHH]);

    // A = d^16
    float A = d;
#pragma unroll
    for (int s = 0; s < 4; s++) A = A * A;

    // Warp-level inclusive Kogge-Stone scan of affine maps (a,b): e -> a*e+b
    float a = A, bq = ema;
#pragma unroll
    for (int off = 1; off < 32; off <<= 1) {
        float ap = __shfl_up_sync(0xffffffffu, a, off);
        float bp = __shfl_up_sync(0xffffffffu, bq, off);
        if (lane >= off) { bq = a * bp + bq; a = a * ap; }
    }

    // Warp aggregates -> smem
    __shared__ float sa[8], sb[8], smax[8];
    if (lane == 31) { sa[wid] = a; sb[wid] = bq; }
    __syncthreads();

    // Exclusive prefix across warps (8 elems, computed redundantly per thread)
    float e_w = 0.0f;
#pragma unroll
    for (int w = 0; w < 8; w++)
        if (w < wid) e_w = sa[w] * e_w + sb[w];

    // Exclusive lane prefix within warp, composed with warp prefix
    float a_ex = __shfl_up_sync(0xffffffffu, a, 1);
    float b_ex = __shfl_up_sync(0xffffffffu, bq, 1);
    float e_in = (lane == 0) ? e_w : (a_ex * e_w + b_ex);

    // Pass 2: replay with incoming state, track max (init 0 per reference)
    ema = e_in;
    float emax = 0.0f;
#pragma unroll
    for (int i = 0; i < CH; i++) {
        ema = d * ema + od * __ldg(&hp[(t0 + i) * NHH]);
        emax = fmaxf(emax, ema);
    }

    // Block max reduce
#pragma unroll
    for (int off = 16; off > 0; off >>= 1)
        emax = fmaxf(emax, __shfl_xor_sync(0xffffffffu, emax, off));
    if (lane == 0) smax[wid] = emax;
    __syncthreads();
    if (tid == 0) {
        float m = smax[0];
#pragma unroll
        for (int w = 1; w < 8; w++) m = fmaxf(m, smax[w]);
        g_part[b * NHH + n] = m;
    }
}

// ---------------------------------------------------------------------------
// Kernel 3: tiny head projection: out[b] = sum_n g_part[b,n] * head_w[n]
// ---------------------------------------------------------------------------
__global__ void k_final(const float* __restrict__ head_w,
                        float* __restrict__ out) {
    int b = threadIdx.x;
    if (b < BB) {
        float s = 0.0f;
#pragma unroll
        for (int n = 0; n < NHH; n++)
            s += g_part[b * NHH + n] * head_w[n];
        out[b] = s;
    }
}

// ---------------------------------------------------------------------------
extern "C" void kernel_launch(void* const* d_in, const int* in_sizes, int n_in,
                              void* d_out, int out_size) {
    const float* x      = (const float*)d_in[0];
    const float* W      = (const float*)d_in[1];
    const float* bias   = (const float*)d_in[2];
    const float* decay  = (const float*)d_in[3];
    const float* head_w = (const float*)d_in[4];
    float* out = (float*)d_out;

    int warps = (BB * TT) / 4;
    int blocks = (warps * 32) / 256;
    k_gemv<<<blocks, 256>>>(x, W, bias);
    dim3 sg(BB, NHH);
    k_scan<<<sg, 256>>>(decay);
    k_final<<<1, 64>>>(head_w, out);
}